// round 14
// baseline (speedup 1.0000x reference)
#include <cuda_runtime.h>
#include <math.h>

#define HH 512
#define WW 512
#define CHW 128
#define FHW 256
#define CF 256
#define NCc 3
#define NPTS 2048
#define NUM_OVER 6144
#define CHUNK 6
#define STEP1 1536
#define STEP2 512
#define BB 2
#define FEAT_DIM 259
#define FEAT_PAD 260
#define NCB1 65
#define NROWS (BB*NPTS)
#define FINE_FLAT (BB*NPTS*CF)
#define OUT_OFF (BB*NCc*NPTS)
#define MASK_SIZE (BB*HH*WW)
#define RPB 16
#define HPAIR 4
#define HTILE (HPAIR*FEAT_PAD*2)
#define NWORDS (HH*WW/32)
#define W1P_ELEMS (NCB1*256*4)
#define W2P_ELEMS (NCB1*128*4)
#define UNC_BLOCKS 12
#define REPACK_BLOCKS 98

// ---------------- device scratch ----------------
__device__ int          g_pts[BB*NPTS];
__device__ unsigned int g_okey[BB*NUM_OVER];
__device__ float        g_cflat[BB*NPTS*NCc];
__device__ float        g_flat[FINE_FLAT];
__device__ float        g_w1p[W1P_ELEMS];
__device__ float        g_w2p[W2P_ELEMS];

// ---------------- f32x2 helpers ----------------
__device__ __forceinline__ unsigned long long pk2(float lo, float hi) {
    unsigned long long r;
    asm("mov.b64 %0, {%1,%2};" : "=l"(r) : "f"(lo), "f"(hi));
    return r;
}
__device__ __forceinline__ void upk2(unsigned long long v, float& lo, float& hi) {
    asm("mov.b64 {%0,%1}, %2;" : "=f"(lo), "=f"(hi) : "l"(v));
}
__device__ __forceinline__ void fma2(unsigned long long& d, unsigned long long a,
                                     unsigned long long b) {
    asm("fma.rn.f32x2 %0, %1, %2, %0;" : "+l"(d) : "l"(a), "l"(b));
}

// =========================================================================
// k_unc (unchanged): blocks 0..11 uncertainty keys; blocks 12.. repack.
// =========================================================================
__global__ __launch_bounds__(1024) void k_unc(const float* __restrict__ coarse,
                                              const int* __restrict__ rnd,
                                              const float* __restrict__ w1,
                                              const float* __restrict__ w2) {
    if (blockIdx.x >= UNC_BLOCKS) {
        int t = (blockIdx.x - UNC_BLOCKS) * 1024 + threadIdx.x;
        if (t < W1P_ELEMS) {
            int cb = t >> 10, rest = t & 1023;
            int o = rest >> 2, q = rest & 3, c = cb * 4 + q;
            g_w1p[t] = (c < FEAT_DIM) ? w1[o*FEAT_DIM + c] : 0.f;
        } else {
            int t2 = t - W1P_ELEMS;
            if (t2 < W2P_ELEMS) {
                int cb = t2 >> 9, rest = t2 & 511;
                int o = rest >> 2, q = rest & 3, c = cb * 4 + q;
                g_w2p[t2] = (c < FEAT_DIM) ? w2[o*FEAT_DIM + c] : 0.f;
            }
        }
        return;
    }
    int t = blockIdx.x * 1024 + threadIdx.x;
    int b = t / NUM_OVER, j = t - b * NUM_OVER;
    int idx = rnd[j];
    int h = idx / WW, w = idx % WW;
    float yc = (float)h * 0.25f - 0.375f;
    float xc = (float)w * 0.25f - 0.375f;
    int y0 = (int)floorf(yc); float fy = yc - (float)y0;
    int x0 = (int)floorf(xc); float fx = xc - (float)x0;
    int y0c = min(max(y0,   0), CHW-1), y1c = min(max(y0+1, 0), CHW-1);
    int x0c = min(max(x0,   0), CHW-1), x1c = min(max(x0+1, 0), CHW-1);
    float p[3];
    const float* base = coarse + (size_t)b * NCc * CHW * CHW;
#pragma unroll
    for (int c = 0; c < 3; c++) {
        const float* pc = base + c * CHW * CHW;
        float v00 = pc[y0c*CHW + x0c], v01 = pc[y0c*CHW + x1c];
        float v10 = pc[y1c*CHW + x0c], v11 = pc[y1c*CHW + x1c];
        float top = v00 * (1.f - fx) + v01 * fx;
        float bot = v10 * (1.f - fx) + v11 * fx;
        p[c] = top * (1.f - fy) + bot * fy;
    }
    float m  = fmaxf(p[0], fmaxf(p[1], p[2]));
    float e0 = expf(p[0]-m), e1 = expf(p[1]-m), e2 = expf(p[2]-m);
    float s  = e0 + e1 + e2;
    float q0 = e0/s, q1 = e1/s, q2 = e2/s;
    float mx  = fmaxf(q0, fmaxf(q1, q2));
    float mn  = fminf(q0, fminf(q1, q2));
    float mid = q0 + q1 + q2 - mx - mn;
    float u = 1.0f - (mx - mid);
    unsigned int bits = __float_as_uint(u);
    g_okey[t] = bits ^ ((bits >> 31) ? 0xFFFFFFFFu : 0x80000000u);
}

// =========================================================================
// k_sel (unchanged): 2 blocks, radix threshold + bitmap + ordered emit.
// =========================================================================
__global__ __launch_bounds__(1024) void k_sel(const int* __restrict__ rnd,
                                              float* __restrict__ mask_out) {
    extern __shared__ unsigned int dyn[];
    __shared__ int hist[256];
    __shared__ int sfxsum[257];
    __shared__ int warp_tot[32];
    __shared__ unsigned int s_prefix;
    __shared__ int s_need;

    int b = blockIdx.x;
    int tid = threadIdx.x;
    int lane = tid & 31, wrp = tid >> 5;

    for (int j = tid; j < NUM_OVER; j += 1024)
        dyn[j] = g_okey[b*NUM_OVER + j];
    if (tid == 0) { s_prefix = 0u; s_need = STEP1; }
    __syncthreads();

    for (int lvl = 0; lvl < 4; lvl++) {
        int shift = 24 - 8*lvl;
        unsigned int hi_mask = lvl ? (0xFFFFFFFFu << (shift + 8)) : 0u;
        unsigned int pref = s_prefix;
        int need = s_need;
        if (tid < 256) hist[tid] = 0;
        __syncthreads();
#pragma unroll
        for (int jj = 0; jj < CHUNK; jj++) {
            unsigned int ok = dyn[tid*CHUNK + jj];
            if ((ok & hi_mask) == pref) atomicAdd(&hist[(ok >> shift) & 255], 1);
        }
        __syncthreads();
        int x = (tid < 256) ? hist[255 - tid] : 0;
#pragma unroll
        for (int o = 1; o < 32; o <<= 1) {
            int y = __shfl_up_sync(0xFFFFFFFFu, x, o);
            if (lane >= o) x += y;
        }
        if (tid < 256 && lane == 31) warp_tot[wrp] = x;
        __syncthreads();
        if (tid < 256) {
            int basew = 0;
            for (int wq = 0; wq < wrp; wq++) basew += warp_tot[wq];
            sfxsum[255 - tid] = x + basew;
        }
        __syncthreads();
        if (tid < 256) {
            int S  = sfxsum[tid];
            int S1 = (tid == 255) ? 0 : sfxsum[tid + 1];
            if (S >= need && S1 < need) {
                s_prefix = pref | ((unsigned int)tid << shift);
                s_need = need - S1;
            }
        }
        __syncthreads();
    }
    unsigned int T = s_prefix;
    int need = s_need;

    unsigned int okv[CHUNK];
    int localeq = 0;
#pragma unroll
    for (int jj = 0; jj < CHUNK; jj++) {
        okv[jj] = dyn[tid*CHUNK + jj];
        localeq += (okv[jj] == T);
    }
    {
        int x = localeq;
#pragma unroll
        for (int o = 1; o < 32; o <<= 1) {
            int y = __shfl_up_sync(0xFFFFFFFFu, x, o);
            if (lane >= o) x += y;
        }
        if (lane == 31) warp_tot[wrp] = x;
        __syncthreads();
        int basew = 0;
        for (int wq = 0; wq < wrp; wq++) basew += warp_tot[wq];
        int rank = basew + x - localeq;
        unsigned int selmask = 0;
#pragma unroll
        for (int jj = 0; jj < CHUNK; jj++) {
            bool sel = okv[jj] > T;
            if (okv[jj] == T) { sel = (rank < need); rank++; }
            if (sel) selmask |= 1u << jj;
        }
        __syncthreads();
        for (int w = tid; w < NWORDS; w += 1024) dyn[w] = 0u;
        __syncthreads();
#pragma unroll
        for (int jj = 0; jj < CHUNK; jj++)
            if ((selmask >> jj) & 1u) {
                int lin = rnd[tid*CHUNK + jj];
                atomicOr(&dyn[lin >> 5], 1u << (lin & 31));
            }
    }
    for (int i = tid; i < STEP2; i += 1024) {
        int lin = rnd[HH*WW - STEP2 + i];
        atomicOr(&dyn[lin >> 5], 1u << (lin & 31));
    }
    __syncthreads();

    {
        int w0 = tid * 8;
        unsigned int words[8];
        int cnt = 0;
#pragma unroll
        for (int q = 0; q < 8; q++) { words[q] = dyn[w0 + q]; cnt += __popc(words[q]); }
        int incl = cnt;
#pragma unroll
        for (int o = 1; o < 32; o <<= 1) {
            int v = __shfl_up_sync(0xFFFFFFFFu, incl, o);
            if (lane >= o) incl += v;
        }
        if (lane == 31) warp_tot[wrp] = incl;
        __syncthreads();
        int basew = 0;
        for (int wq = 0; wq < wrp; wq++) basew += warp_tot[wq];
        int offset = basew + incl - cnt;
#pragma unroll
        for (int q = 0; q < 8; q++) {
            unsigned int m = words[q];
            int linbase = (w0 + q) * 32;
            while (m) {
                int bpos = __ffs(m) - 1; m &= m - 1;
                int lin = linbase + bpos;
                g_pts[b*NPTS + offset] = lin;
                mask_out[b*HH*WW + lin] = 1.0f;
                offset++;
            }
        }
    }
}

// =========================================================================
// k_sample (unchanged): one block per point, 256 threads = channels.
// =========================================================================
__global__ __launch_bounds__(256) void k_sample(const float* __restrict__ fine,
                                                const float* __restrict__ coarse) {
    int g = blockIdx.x;
    int b = g >> 11;
    int ch = threadIdx.x;
    int idx = g_pts[g];
    int h = idx >> 9, w = idx & 511;
    float yf = (float)h * 0.5f - 0.25f;
    float xf = (float)w * 0.5f - 0.25f;
    int y0 = (int)floorf(yf); float sfy = yf - (float)y0;
    int x0 = (int)floorf(xf); float sfx = xf - (float)x0;
    int sy0 = min(max(y0,   0), FHW-1), sy1 = min(max(y0+1, 0), FHW-1);
    int sx0 = min(max(x0,   0), FHW-1), sx1 = min(max(x0+1, 0), FHW-1);
    const float* pf = fine + ((size_t)b * CF + ch) * (FHW * FHW);
    float v00, v01, v10, v11;
    if ((sx1 == sx0 + 1) && ((sx0 & 1) == 0)) {
        float2 aa = *(const float2*)(pf + sy0*FHW + sx0);
        float2 dd = *(const float2*)(pf + sy1*FHW + sx0);
        v00 = aa.x; v01 = aa.y; v10 = dd.x; v11 = dd.y;
    } else {
        v00 = pf[sy0*FHW + sx0]; v01 = pf[sy0*FHW + sx1];
        v10 = pf[sy1*FHW + sx0]; v11 = pf[sy1*FHW + sx1];
    }
    float top = v00 * (1.f - sfx) + v01 * sfx;
    float bot = v10 * (1.f - sfx) + v11 * sfx;
    g_flat[(size_t)g * CF + ch] = top * (1.f - sfy) + bot * sfy;

    if (ch < NCc) {
        float yc = (float)h * 0.25f - 0.375f;
        float xc = (float)w * 0.25f - 0.375f;
        int cy = (int)floorf(yc); float cfy = yc - (float)cy;
        int cx = (int)floorf(xc); float cfx = xc - (float)cx;
        int cy0 = min(max(cy,   0), CHW-1), cy1 = min(max(cy+1, 0), CHW-1);
        int cx0 = min(max(cx,   0), CHW-1), cx1 = min(max(cx+1, 0), CHW-1);
        const float* pc = coarse + ((size_t)b * NCc + ch) * (CHW * CHW);
        float c00 = pc[cy0*CHW + cx0], c01 = pc[cy0*CHW + cx1];
        float c10 = pc[cy1*CHW + cx0], c11 = pc[cy1*CHW + cx1];
        float ctop = c00 * (1.f - cfx) + c01 * cfx;
        float cbot = c10 * (1.f - cfx) + c11 * cfx;
        g_cflat[g*NCc + ch] = ctop * (1.f - cfy) + cbot * cfy;
    }
}

// =========================================================================
// k_mlp: 512 threads, two independent 8-row halves per block.
// Layer 1 NEW: each thread computes 2 outputs (o, o+128) x 2 pairs -> the
// 4 feature LDS.128 per cb are shared across both outputs (LDS:FMA 1:4,
// half the smem wavefronts of R13). Accumulation order per (row, output)
// unchanged -> bit-identical. Layer 2/3 as R13.
// =========================================================================
__global__ __launch_bounds__(512) void k_mlp(const float* __restrict__ w3,
                                             const float* __restrict__ pa,
                                             float* __restrict__ out) {
    extern __shared__ float sm[];
    float* xsp = sm;                         // 2 halves x 4 pairs x 260 x2
    float* l1p = xsp + 2*HTILE;
    float* l2s = l1p + 2*HTILE;              // 16 x 128
    float* w3s = l2s + RPB*128;              // 396 (+4)

    int tid = threadIdx.x;
    int g0 = blockIdx.x * RPB;
    float a = *pa;

    // ---- load rows (coalesced) into per-half pair tiles ----
    for (int q = tid; q < RPB*FEAT_PAD; q += 512) {
        int r = q / FEAT_PAD, c = q - r*FEAT_PAD;
        float v = 0.f;
        if (c < FEAT_DIM) {
            int f = (g0 + r) * FEAT_DIM + c;
            v = (f < FINE_FLAT) ? g_flat[f] : g_cflat[f - FINE_FLAT];
        }
        int hh = r >> 3, rl = r & 7;
        int pi = hh*HTILE + ((rl >> 1) * FEAT_PAD + c) * 2 + (rl & 1);
        xsp[pi] = v;
        if (c >= 256) l1p[pi] = v;
    }
    for (int q = tid; q < NCc*131; q += 512) w3s[q] = w3[q];
    __syncthreads();

    // ---- layer 1: 259 -> 256, prelu. 2 outputs x 2 pairs per thread ----
    {
        int t1 = tid & 127;                  // output base
        int qg = tid >> 7;                   // 0..3
        int hf1 = qg >> 1;                   // half
        int pg  = qg & 1;                    // pair-group: pairs 2pg, 2pg+1
        const float* xh1 = xsp + hf1*HTILE;
        float* lh1 = l1p + hf1*HTILE;
        int pr0 = pg*2, pr1 = pg*2 + 1;
        const ulonglong2* xq0 = (const ulonglong2*)&xh1[pr0*FEAT_PAD*2];
        const ulonglong2* xq1 = (const ulonglong2*)&xh1[pr1*FEAT_PAD*2];
        int o0 = t1, o1 = t1 + 128;
        unsigned long long a00 = 0ull, a01 = 0ull, a10 = 0ull, a11 = 0ull;
        const float4* w1p4 = (const float4*)g_w1p;

#define L1V2(CB, WA, WB) do {                                                \
            ulonglong2 u0 = xq0[2*(CB)], u1 = xq0[2*(CB)+1];                 \
            ulonglong2 v0 = xq1[2*(CB)], v1 = xq1[2*(CB)+1];                 \
            unsigned long long wa0 = pk2((WA).x,(WA).x),                     \
                               wa1 = pk2((WA).y,(WA).y),                     \
                               wa2 = pk2((WA).z,(WA).z),                     \
                               wa3 = pk2((WA).w,(WA).w);                     \
            unsigned long long wb0 = pk2((WB).x,(WB).x),                     \
                               wb1 = pk2((WB).y,(WB).y),                     \
                               wb2 = pk2((WB).z,(WB).z),                     \
                               wb3 = pk2((WB).w,(WB).w);                     \
            fma2(a00, wa0, u0.x); fma2(a00, wa1, u0.y);                      \
            fma2(a00, wa2, u1.x); fma2(a00, wa3, u1.y);                      \
            fma2(a01, wa0, v0.x); fma2(a01, wa1, v0.y);                      \
            fma2(a01, wa2, v1.x); fma2(a01, wa3, v1.y);                      \
            fma2(a10, wb0, u0.x); fma2(a10, wb1, u0.y);                      \
            fma2(a10, wb2, u1.x); fma2(a10, wb3, u1.y);                      \
            fma2(a11, wb0, v0.x); fma2(a11, wb1, v0.y);                      \
            fma2(a11, wb2, v1.x); fma2(a11, wb3, v1.y);                      \
        } while (0)

        for (int cb0 = 0; cb0 < 64; cb0 += 4) {
            float4 wA0 = w1p4[(cb0+0)*256 + o0], wB0 = w1p4[(cb0+0)*256 + o1];
            float4 wA1 = w1p4[(cb0+1)*256 + o0], wB1 = w1p4[(cb0+1)*256 + o1];
            float4 wA2 = w1p4[(cb0+2)*256 + o0], wB2 = w1p4[(cb0+2)*256 + o1];
            float4 wA3 = w1p4[(cb0+3)*256 + o0], wB3 = w1p4[(cb0+3)*256 + o1];
            L1V2(cb0+0, wA0, wB0); L1V2(cb0+1, wA1, wB1);
            L1V2(cb0+2, wA2, wB2); L1V2(cb0+3, wA3, wB3);
        }
        { float4 wA = w1p4[64*256 + o0], wB = w1p4[64*256 + o1]; L1V2(64, wA, wB); }
#undef L1V2

        float lo, hi;
        upk2(a00, lo, hi);
        lo = lo >= 0.f ? lo : a*lo; hi = hi >= 0.f ? hi : a*hi;
        ((float2*)lh1)[pr0*FEAT_PAD + o0] = make_float2(lo, hi);
        upk2(a01, lo, hi);
        lo = lo >= 0.f ? lo : a*lo; hi = hi >= 0.f ? hi : a*hi;
        ((float2*)lh1)[pr1*FEAT_PAD + o0] = make_float2(lo, hi);
        upk2(a10, lo, hi);
        lo = lo >= 0.f ? lo : a*lo; hi = hi >= 0.f ? hi : a*hi;
        ((float2*)lh1)[pr0*FEAT_PAD + o1] = make_float2(lo, hi);
        upk2(a11, lo, hi);
        lo = lo >= 0.f ? lo : a*lo; hi = hi >= 0.f ? hi : a*hi;
        ((float2*)lh1)[pr1*FEAT_PAD + o1] = make_float2(lo, hi);
    }
    __syncthreads();

    // ---- layer 2: 259 -> 128, prelu (R13 scheme: 2 pairs per thread) ----
    {
        int hf = tid >> 8;
        int t  = tid & 255;
        float* lh = l1p + hf*HTILE;
        int o2 = t & 127;
        int rh = t >> 7;
        unsigned long long acc2[2];
        acc2[0] = 0ull; acc2[1] = 0ull;
        const float4* w2p4 = (const float4*)g_w2p;

#define L2_CB(CB, WV) do {                                                   \
            unsigned long long wp0 = pk2((WV).x, (WV).x),                    \
                               wp1 = pk2((WV).y, (WV).y),                    \
                               wp2 = pk2((WV).z, (WV).z),                    \
                               wp3 = pk2((WV).w, (WV).w);                    \
            _Pragma("unroll")                                                \
            for (int pp = 0; pp < 2; pp++) {                                 \
                int pr = rh*2 + pp;                                          \
                const ulonglong2* xp =                                       \
                    (const ulonglong2*)&lh[(pr*FEAT_PAD + (CB)*4) * 2];      \
                ulonglong2 u0 = xp[0], u1 = xp[1];                           \
                fma2(acc2[pp], wp0, u0.x);                                   \
                fma2(acc2[pp], wp1, u0.y);                                   \
                fma2(acc2[pp], wp2, u1.x);                                   \
                fma2(acc2[pp], wp3, u1.y);                                   \
            }                                                                \
        } while (0)

        for (int cb0 = 0; cb0 < 64; cb0 += 4) {
            float4 a0 = w2p4[(cb0+0)*128 + o2];
            float4 a1 = w2p4[(cb0+1)*128 + o2];
            float4 a2 = w2p4[(cb0+2)*128 + o2];
            float4 a3 = w2p4[(cb0+3)*128 + o2];
            L2_CB(cb0+0, a0); L2_CB(cb0+1, a1);
            L2_CB(cb0+2, a2); L2_CB(cb0+3, a3);
        }
        { float4 a4 = w2p4[64*128 + o2]; L2_CB(64, a4); }
#undef L2_CB

#pragma unroll
        for (int pp = 0; pp < 2; pp++) {
            int pr = rh*2 + pp;
            float lo, hi; upk2(acc2[pp], lo, hi);
            lo = lo >= 0.f ? lo : a * lo;
            hi = hi >= 0.f ? hi : a * hi;
            l2s[hf*1024 + (2*pr  )*128 + o2] = lo;
            l2s[hf*1024 + (2*pr+1)*128 + o2] = hi;
        }
    }
    __syncthreads();

    // ---- layer 3: 131 -> 3 ----
    {
        int hf = tid >> 8;
        int t  = tid & 255;
        if (t < 8*NCc) {
            const float* xh = xsp + hf*HTILE;
            int r = t / 3, oo = t % 3;
            float s = 0.f;
            for (int c = 0; c < 128; c++)
                s = fmaf(w3s[oo*131 + c], l2s[hf*1024 + r*128 + c], s);
#pragma unroll
            for (int q = 0; q < 3; q++) {
                float xt = xh[((r >> 1)*FEAT_PAD + 256 + q)*2 + (r & 1)];
                s = fmaf(w3s[oo*131 + 128 + q], xt, s);
            }
            int g = g0 + hf*8 + r;
            int b = g >> 11, n = g & 2047;
            out[(b*NCc + oo)*NPTS + n] = s;
        }
    }
}

// ---------------- launch ----------------
extern "C" void kernel_launch(void* const* d_in, const int* in_sizes, int n_in,
                              void* d_out, int out_size) {
    const float* fine   = (const float*)d_in[0];
    const float* coarse = (const float*)d_in[1];
    const float* w1     = (const float*)d_in[2];
    const float* w2     = (const float*)d_in[3];
    const float* w3     = (const float*)d_in[4];
    const float* pa     = (const float*)d_in[5];
    const int*   rnd    = (const int*)d_in[6];
    float* out = (float*)d_out;

    static int configured = 0;
    int mlp_smem = (2*HTILE*2 + RPB*128 + 400) * (int)sizeof(float);
    if (!configured) {
        cudaFuncSetAttribute(k_sel, cudaFuncAttributeMaxDynamicSharedMemorySize,
                             NWORDS * (int)sizeof(unsigned int));
        cudaFuncSetAttribute(k_mlp, cudaFuncAttributeMaxDynamicSharedMemorySize,
                             mlp_smem);
        configured = 1;
    }

    cudaMemsetAsync(out + OUT_OFF, 0, (size_t)MASK_SIZE * sizeof(float), 0);
    k_unc<<<UNC_BLOCKS + REPACK_BLOCKS, 1024>>>(coarse, rnd, w1, w2);
    k_sel<<<BB, 1024, NWORDS * sizeof(unsigned int)>>>(rnd, out + OUT_OFF);
    k_sample<<<NROWS, 256>>>(fine, coarse);
    k_mlp<<<NROWS/RPB, 512, mlp_smem>>>(w3, pa, out);
    (void)in_sizes; (void)n_in; (void)out_size;
}